// round 15
// baseline (speedup 1.0000x reference)
#include <cuda_runtime.h>
#include <cuda.h>
#include <cuda_fp16.h>
#include <cstdint>

#define M_DIM 16384
#define N_DIM 4096
#define K_DIM 4096
#define R_DIM 16
#define KA    4160   // K augmented: 4096 base + 16 low-rank + 48 zero pad

// ---- device scratch (module-load allocated; no runtime allocs) ----
__device__ float g_W2 [N_DIM * R_DIM];
__device__ float g_G  [R_DIM * R_DIM];
__device__ float g_d  [N_DIM * R_DIM];
__device__ float g_nb [N_DIM];
__device__ __half g_xa[(size_t)M_DIM * KA];   // [x_fp16 | t | 0pad]
__device__ __half g_wa[(size_t)N_DIM * KA];   // [(sc-1)*w_fp16 | sc*W2 | 0pad]

__device__ __forceinline__ uint32_t smem_u32(const void* p) {
  uint32_t a;
  asm("{ .reg .u64 t; cvta.to.shared.u64 t, %1; cvt.u32.u64 %0, t; }" : "=r"(a) : "l"(p));
  return a;
}
__device__ __forceinline__ void bar_init(uint32_t a, uint32_t cnt) {
  asm volatile("mbarrier.init.shared.b64 [%0], %1;" :: "r"(a), "r"(cnt) : "memory");
}
__device__ __forceinline__ void bar_arrive(uint32_t a) {
  asm volatile("mbarrier.arrive.shared.b64 _, [%0];" :: "r"(a) : "memory");
}
__device__ __forceinline__ void bar_expect_tx(uint32_t a, uint32_t tx) {
  asm volatile("mbarrier.arrive.expect_tx.shared.b64 _, [%0], %1;" :: "r"(a), "r"(tx) : "memory");
}
__device__ __forceinline__ void bar_wait(uint32_t a, uint32_t parity) {
  asm volatile(
    "{\n\t.reg .pred P;\n\t"
    "BW_%=:\n\t"
    "mbarrier.try_wait.parity.shared.b64 P, [%0], %1, 0x989680;\n\t"
    "@!P bra BW_%=;\n\t}"
    :: "r"(a), "r"(parity) : "memory");
}
__device__ __forceinline__ void tma2d(uint32_t dst, const void* map, int cx, int cy, uint32_t bar) {
  asm volatile(
    "cp.async.bulk.tensor.2d.shared::cluster.global.tile.mbarrier::complete_tx::bytes "
    "[%0], [%1, {%2, %3}], [%4];"
    :: "r"(dst), "l"(map), "r"(cx), "r"(cy), "r"(bar) : "memory");
}

#define SWZ(o) ((o) ^ (((o) >> 3) & 0x70))

#define LDMX4(r, addr)                                                        \
  asm volatile("ldmatrix.sync.aligned.m8n8.x4.shared.b16 {%0,%1,%2,%3}, [%4];"\
               : "=r"((r)[0]), "=r"((r)[1]), "=r"((r)[2]), "=r"((r)[3])       \
               : "r"(addr))

#define MMA16816(d, a, b)                                                     \
  asm volatile("mma.sync.aligned.m16n8k16.row.col.f32.f16.f16.f32 "           \
               "{%0,%1,%2,%3}, {%4,%5,%6,%7}, {%8,%9}, {%0,%1,%2,%3};"        \
               : "+f"((d)[0]), "+f"((d)[1]), "+f"((d)[2]), "+f"((d)[3])       \
               : "r"((a)[0]), "r"((a)[1]), "r"((a)[2]), "r"((a)[3]),          \
                 "r"((b)[0]), "r"((b)[1]))

// ============================================================
// k_pre: W2 = O*U*S (blocks 0..255) ; G = V V^T (blocks 256..511)
// ============================================================
__global__ void k_pre(const float* __restrict__ U, const float* __restrict__ V,
                      const float* __restrict__ S, const float* __restrict__ O) {
  const int b = blockIdx.x, tid = threadIdx.x;
  if (b < 256) {
    int idx = b * 256 + tid;
    int o = idx >> 4, r = idx & 15;
    g_W2[idx] = O[o] * U[idx] * S[r];
  } else {
    const int p = b - 256, r = p >> 4, r2 = p & 15;
    const float4* va = (const float4*)(V + r  * K_DIM);
    const float4* vb = (const float4*)(V + r2 * K_DIM);
    float s = 0.f;
    for (int i = tid; i < 1024; i += 256) {
      float4 a = va[i], c = vb[i];
      s += a.x * c.x + a.y * c.y + a.z * c.z + a.w * c.w;
    }
    __shared__ float red[256];
    red[tid] = s; __syncthreads();
#pragma unroll
    for (int st = 128; st; st >>= 1) {
      if (tid < st) red[tid] += red[tid + st];
      __syncthreads();
    }
    if (tid == 0) g_G[p] = red[0];
  }
}

// ============================================================
// k_t2: fused split + rowdot. 64 rows/block, 128 threads, 4 warps.
// blocks 0..255 : x fp32 -> fp16 (g_xa + smem), t = x@Vh^T -> g_xa cols 4096+
// blocks 256..319: W fp32 -> fp16 (g_wa + smem), d -> g_d, ||row||^2 -> g_nb
// V converted from fp32 per chunk (L2-resident). Pads zeroed here.
// fp16 values and MMA accumulation order identical to R14 -> same results.
// ============================================================
__global__ void __launch_bounds__(128) k_t2(const float* __restrict__ x,
                                            const float* __restrict__ W,
                                            const float* __restrict__ V) {
  __shared__ __align__(16) __half As[64 * 72];
  __shared__ __align__(16) __half Vs[16 * 72];
  const int tid = threadIdx.x, lane = tid & 31, warp = tid >> 5;
  const bool isw = blockIdx.x >= 256;
  const int row0 = (isw ? (int)blockIdx.x - 256 : (int)blockIdx.x) * 64;
  const float* A = isw ? W : x;
  __half* dstg = isw ? g_wa : g_xa;

  const int rr = tid >> 3;        // 0..15
  const int q  = tid & 7;         // 0..7  (8 halfs = 32B fp32 per (r,q))

  float acc[2][4];
#pragma unroll
  for (int i = 0; i < 2; ++i)
#pragma unroll
    for (int e = 0; e < 4; ++e) acc[i][e] = 0.f;
  float nacc[4] = {0.f, 0.f, 0.f, 0.f};

  const int arow = lane & 15, acol = (lane >> 4) << 3;
  const int brow = (lane & 7) + ((lane >> 4) << 3), bcol = ((lane >> 3) & 1) << 3;
  const uint32_t aB = smem_u32(As);
  const uint32_t bB = smem_u32(Vs);

  for (int kc = 0; kc < 64; ++kc) {
    const int k0 = kc * 64;
    // ---- load fp32, convert, store smem + gmem fp16 ----
#pragma unroll
    for (int i = 0; i < 4; ++i) {
      const int r = i * 16 + rr;
      const float4* src = (const float4*)(A + (size_t)(row0 + r) * K_DIM + k0 + q * 8);
      float4 v0 = src[0], v1 = src[1];
      if (isw)
        nacc[i] += v0.x * v0.x + v0.y * v0.y + v0.z * v0.z + v0.w * v0.w +
                   v1.x * v1.x + v1.y * v1.y + v1.z * v1.z + v1.w * v1.w;
      union { __half2 h[4]; uint4 u; } H;
      H.h[0] = __floats2half2_rn(v0.x, v0.y);
      H.h[1] = __floats2half2_rn(v0.z, v0.w);
      H.h[2] = __floats2half2_rn(v1.x, v1.y);
      H.h[3] = __floats2half2_rn(v1.z, v1.w);
      *(uint4*)&As[r * 72 + q * 8] = H.u;
      *(uint4*)(dstg + (size_t)(row0 + r) * KA + k0 + q * 8) = H.u;
    }
    {
      const float4* src = (const float4*)(V + (size_t)rr * K_DIM + k0 + q * 8);
      float4 v0 = src[0], v1 = src[1];
      union { __half2 h[4]; uint4 u; } H;
      H.h[0] = __floats2half2_rn(v0.x, v0.y);
      H.h[1] = __floats2half2_rn(v0.z, v0.w);
      H.h[2] = __floats2half2_rn(v1.x, v1.y);
      H.h[3] = __floats2half2_rn(v1.z, v1.w);
      *(uint4*)&Vs[rr * 72 + q * 8] = H.u;
    }
    __syncthreads();
    // ---- MMA (identical layout/order to R14 k_t) ----
#pragma unroll
    for (int kk = 0; kk < 4; ++kk) {
      uint32_t a[4], bt[4];
      LDMX4(a, aB + (uint32_t)((warp * 16 + arow) * 72 + kk * 16 + acol) * 2);
      LDMX4(bt, bB + (uint32_t)(brow * 72 + kk * 16 + bcol) * 2);
      uint32_t b0[2] = {bt[0], bt[1]}, b1[2] = {bt[2], bt[3]};
      MMA16816(acc[0], a, b0);
      MMA16816(acc[1], a, b1);
    }
    __syncthreads();
  }

  // ---- norm reduce + store (W blocks) ----
  if (isw) {
#pragma unroll
    for (int i = 0; i < 4; ++i) {
      float v = nacc[i];
#pragma unroll
      for (int off = 4; off; off >>= 1) v += __shfl_xor_sync(0xffffffffu, v, off);
      if (q == 0) g_nb[row0 + i * 16 + rr] = v;
    }
  }

  // ---- t / d store ----
  const int r1 = row0 + warp * 16 + (lane >> 2);
#pragma unroll
  for (int nt = 0; nt < 2; ++nt) {
    const int c = nt * 8 + 2 * (lane & 3);
    if (isw) {
      *(float2*)&g_d[(size_t)r1 * 16 + c]       = make_float2(acc[nt][0], acc[nt][1]);
      *(float2*)&g_d[(size_t)(r1 + 8) * 16 + c] = make_float2(acc[nt][2], acc[nt][3]);
    } else {
      *(__half2*)&g_xa[(size_t)r1 * KA + 4096 + c]       = __floats2half2_rn(acc[nt][0], acc[nt][1]);
      *(__half2*)&g_xa[(size_t)(r1 + 8) * KA + 4096 + c] = __floats2half2_rn(acc[nt][2], acc[nt][3]);
    }
  }

  // ---- zero pads: cols 4112..4159 (6 x uint4 per row) ----
#pragma unroll
  for (int j = 0; j < 3; ++j) {
    const int idx = j * 128 + tid;        // 0..383
    const int r = idx / 6, p = idx % 6;
    *(uint4*)(dstg + (size_t)(row0 + r) * KA + 4112 + p * 8) = make_uint4(0, 0, 0, 0);
  }
}

// ============================================================
// k_sw: merged scale + wscale, one warp per row (unchanged).
// ============================================================
__global__ void k_sw(const float* __restrict__ mag) {
  const int lane = threadIdx.x & 31, warp = threadIdx.x >> 5;
  const int row = blockIdx.x * 8 + warp;

  float p = 0.f;
  if (lane < 16) {
    const float w2r = g_W2[row * 16 + lane];
    float gsum = 0.f;
#pragma unroll
    for (int r2 = 0; r2 < 16; ++r2)
      gsum += g_G[lane * 16 + r2] * g_W2[row * 16 + r2];
    p = w2r * (2.f * g_d[row * 16 + lane] + gsum);
  }
#pragma unroll
  for (int off = 16; off; off >>= 1) p += __shfl_xor_sync(0xffffffffu, p, off);
  const float sc = mag[row] / sqrtf(g_nb[row] + p);
  const float s = sc - 1.f;

  __half* dst = g_wa + (size_t)row * KA;
#pragma unroll 4
  for (int i = 0; i < 16; ++i) {
    uint4 u = *(uint4*)(dst + (i * 32 + lane) * 8);
    union { __half2 h[4]; uint4 u; } P;
    P.u = u;
#pragma unroll
    for (int j = 0; j < 4; ++j) {
      float2 f = __half22float2(P.h[j]);
      P.h[j] = __floats2half2_rn(f.x * s, f.y * s);
    }
    *(uint4*)(dst + (i * 32 + lane) * 8) = P.u;
  }
  if (lane < 2) {
    union { __half2 h[4]; uint4 u; } P;
#pragma unroll
    for (int j = 0; j < 4; ++j) {
      int r = lane * 8 + j * 2;
      P.h[j] = __floats2half2_rn(sc * g_W2[row * 16 + r], sc * g_W2[row * 16 + r + 1]);
    }
    *(uint4*)(dst + 4096 + lane * 8) = P.u;
  }
}

// ============================================================
// k_gemm_h: EXACT R9/R14 kernel (best measured — do not touch).
// ============================================================
#define BMt 256
#define BNt 128
#define BKh 64
#define NKTt (KA / BKh)                  // 65
#define A_BYTES (BMt * 128)              // 32768
#define B_BYTES (BNt * 128)              // 16384
#define STAGE_B (A_BYTES + B_BYTES)      // 49152
#define NSTG 4
#define GEMM_SMEM (NSTG * STAGE_B + 1024)  // 197632

__global__ void __launch_bounds__(256, 1)
k_gemm_h(const __grid_constant__ CUtensorMap mapA,
         const __grid_constant__ CUtensorMap mapB,
         float* __restrict__ out) {
  extern __shared__ __align__(16) uint8_t dynsm[];
  __shared__ __align__(8) uint64_t s_bar[8];  // full[4], empty[4]

  const int tid  = threadIdx.x;
  const int lane = tid & 31;
  const int warp = tid >> 5;
  const int m_base = (warp >> 1) * 64;
  const int n_base = (warp & 1) * 64;
  const int bM = blockIdx.y * BMt;
  const int bN = blockIdx.x * BNt;

  const uint32_t raw = smem_u32(dynsm);
  const uint32_t smb = (raw + 1023u) & ~1023u;
  const uint32_t barb = smem_u32(s_bar);

  if (tid == 0) {
#pragma unroll
    for (int s = 0; s < NSTG; ++s) {
      bar_init(barb + s * 8, 1);               // full (tx-based)
      bar_init(barb + NSTG * 8 + s * 8, 8);    // empty (one arrive per warp)
    }
  }
  __syncthreads();
  if (lane == 0) {
#pragma unroll
    for (int s = 0; s < NSTG; ++s) bar_arrive(barb + NSTG * 8 + s * 8);  // pre-arm
  }

  // prefill stages 0..2
  if (tid == 0) {
#pragma unroll
    for (int p = 0; p < 3; ++p) {
      const uint32_t fb = barb + p * 8;
      bar_wait(barb + NSTG * 8 + p * 8, 0);
      bar_expect_tx(fb, STAGE_B);
      const uint32_t base = smb + p * STAGE_B;
      tma2d(base,           &mapA, p * BKh, bM, fb);
      tma2d(base + A_BYTES, &mapB, p * BKh, bN, fb);
    }
  }

  float acc[4][8][4];
#pragma unroll
  for (int i = 0; i < 4; ++i)
#pragma unroll
    for (int j = 0; j < 8; ++j)
#pragma unroll
      for (int e = 0; e < 4; ++e) acc[i][j][e] = 0.f;

  const int arow = lane & 15;
  const int ahalf = lane >> 4;
  const int brow = (lane & 7) + ((lane >> 4) << 3);
  const int bhalf = (lane >> 3) & 1;

  uint32_t ah[2][4][4], bh[2][8][2];

  auto lds_frags = [&](int buf, uint32_t aB, uint32_t bB, int kk) {
#pragma unroll
    for (int mt = 0; mt < 4; ++mt) {
      const uint32_t off = (uint32_t)((m_base + mt * 16 + arow) * 128 +
                                      (kk * 2 + ahalf) * 16);
      LDMX4(ah[buf][mt], aB + SWZ(off));
    }
#pragma unroll
    for (int pp = 0; pp < 4; ++pp) {
      const uint32_t off = (uint32_t)((n_base + pp * 16 + brow) * 128 +
                                      (kk * 2 + bhalf) * 16);
      uint32_t r[4];
      LDMX4(r, bB + SWZ(off));
      bh[buf][2 * pp][0] = r[0]; bh[buf][2 * pp][1] = r[1];
      bh[buf][2 * pp + 1][0] = r[2]; bh[buf][2 * pp + 1][1] = r[3];
    }
  };

  for (int kt = 0; kt < NKTt; ++kt) {
    const int p = kt + 3;
    if (tid == 0 && p < NKTt) {
      const int sp = p & 3;
      const uint32_t fb = barb + sp * 8;
      bar_wait(barb + NSTG * 8 + sp * 8, (p >> 2) & 1);
      bar_expect_tx(fb, STAGE_B);
      const uint32_t base = smb + sp * STAGE_B;
      tma2d(base,           &mapA, p * BKh, bM, fb);
      tma2d(base + A_BYTES, &mapB, p * BKh, bN, fb);
    }
    const int s = kt & 3;
    bar_wait(barb + s * 8, (kt >> 2) & 1);

    const uint32_t aB = smb + s * STAGE_B;
    const uint32_t bB = aB + A_BYTES;

    lds_frags(0, aB, bB, 0);
#pragma unroll
    for (int kk = 0; kk < 4; ++kk) {
      const int cur = kk & 1;
      if (kk < 3) lds_frags(cur ^ 1, aB, bB, kk + 1);
#pragma unroll
      for (int mt = 0; mt < 4; ++mt)
#pragma unroll
        for (int nt = 0; nt < 8; ++nt)
          MMA16816(acc[mt][nt], ah[cur][mt], bh[cur][nt]);
    }
    if (lane == 0) bar_arrive(barb + NSTG * 8 + s * 8);
  }

  // ---------------- pure store ----------------
#pragma unroll
  for (int mt = 0; mt < 4; ++mt)
#pragma unroll
    for (int h = 0; h < 2; ++h) {
      const int gm = bM + m_base + mt * 16 + h * 8 + (lane >> 2);
#pragma unroll
      for (int nt = 0; nt < 8; ++nt) {
        const int gn = bN + n_base + nt * 8 + 2 * (lane & 3);
        *(float2*)(out + (size_t)gm * N_DIM + gn) =
            make_float2(acc[mt][nt][h * 2], acc[mt][nt][h * 2 + 1]);
      }
    }
}

// ============================================================
typedef CUresult (*EncTiledFn)(
    CUtensorMap*, CUtensorMapDataType, cuuint32_t, void*,
    const cuuint64_t*, const cuuint64_t*, const cuuint32_t*, const cuuint32_t*,
    CUtensorMapInterleave, CUtensorMapSwizzle, CUtensorMapL2promotion,
    CUtensorMapFloatOOBfill);

extern "C" void kernel_launch(void* const* d_in, const int* in_sizes, int n_in,
                              void* d_out, int out_size) {
  (void)in_sizes; (void)n_in; (void)out_size;
  const float* x   = (const float*)d_in[0];
  const float* U   = (const float*)d_in[1];
  const float* V   = (const float*)d_in[2];
  const float* S   = (const float*)d_in[3];
  const float* O   = (const float*)d_in[4];
  const float* mag = (const float*)d_in[5];
  const float* W   = (const float*)d_in[6];
  float* out = (float*)d_out;

  cudaFuncSetAttribute(k_gemm_h, cudaFuncAttributeMaxDynamicSharedMemorySize, GEMM_SMEM);

  void* fn = nullptr;
  cudaDriverEntryPointQueryResult qr;
  cudaGetDriverEntryPointByVersion("cuTensorMapEncodeTiled", &fn, 12000,
                                   cudaEnableDefault, &qr);
  EncTiledFn enc = (EncTiledFn)fn;
  void *pxa, *pwa;
  cudaGetSymbolAddress(&pxa, g_xa);
  cudaGetSymbolAddress(&pwa, g_wa);

  CUtensorMap mA, mB;
  {
    cuuint64_t dims[2]  = {(cuuint64_t)KA, (cuuint64_t)M_DIM};
    cuuint64_t strd[1]  = {(cuuint64_t)KA * 2};
    cuuint32_t box[2]   = {BKh, BMt};
    cuuint32_t es[2]    = {1, 1};
    enc(&mA, CU_TENSOR_MAP_DATA_TYPE_FLOAT16, 2, pxa, dims, strd, box, es,
        CU_TENSOR_MAP_INTERLEAVE_NONE, CU_TENSOR_MAP_SWIZZLE_128B,
        CU_TENSOR_MAP_L2_PROMOTION_L2_128B, CU_TENSOR_MAP_FLOAT_OOB_FILL_NONE);
  }
  {
    cuuint64_t dims[2]  = {(cuuint64_t)KA, (cuuint64_t)N_DIM};
    cuuint64_t strd[1]  = {(cuuint64_t)KA * 2};
    cuuint32_t box[2]   = {BKh, BNt};
    cuuint32_t es[2]    = {1, 1};
    enc(&mB, CU_TENSOR_MAP_DATA_TYPE_FLOAT16, 2, pwa, dims, strd, box, es,
        CU_TENSOR_MAP_INTERLEAVE_NONE, CU_TENSOR_MAP_SWIZZLE_128B,
        CU_TENSOR_MAP_L2_PROMOTION_L2_128B, CU_TENSOR_MAP_FLOAT_OOB_FILL_NONE);
  }

  k_pre<<<512, 256>>>(U, V, S, O);                // 1 (W2 + G only)
  k_t2<<<320, 128>>>(x, W, V);                    // 2 (fused split+rowdot)
  k_sw<<<N_DIM / 8, 256>>>(mag);                  // 3
  k_gemm_h<<<dim3(N_DIM / BNt, M_DIM / BMt), 256, GEMM_SMEM>>>(mA, mB, out);  // 4 (R9)
}

// round 16
// speedup vs baseline: 1.0519x; 1.0519x over previous
#include <cuda_runtime.h>
#include <cuda.h>
#include <cuda_fp16.h>
#include <cstdint>

#define M_DIM 16384
#define N_DIM 4096
#define K_DIM 4096
#define R_DIM 16
#define KA    4160   // K augmented: 4096 base + 16 low-rank + 48 zero pad

// ---- device scratch (module-load allocated; no runtime allocs) ----
__device__ float g_W2 [N_DIM * R_DIM];
__device__ float g_G  [R_DIM * R_DIM];
__device__ float g_d  [N_DIM * R_DIM];
__device__ float g_nb [N_DIM];
__device__ __half g_vh[R_DIM * K_DIM];
__device__ __half g_xa[(size_t)M_DIM * KA];   // [x_fp16 | t | 0pad]
__device__ __half g_wa[(size_t)N_DIM * KA];   // [(sc-1)*w_fp16 | sc*W2 | 0pad]

__device__ __forceinline__ uint32_t smem_u32(const void* p) {
  uint32_t a;
  asm("{ .reg .u64 t; cvta.to.shared.u64 t, %1; cvt.u32.u64 %0, t; }" : "=r"(a) : "l"(p));
  return a;
}
__device__ __forceinline__ void cpa16(uint32_t dst, const void* src) {
  asm volatile("cp.async.cg.shared.global [%0], [%1], 16;" :: "r"(dst), "l"(src) : "memory");
}
__device__ __forceinline__ void bar_init(uint32_t a, uint32_t cnt) {
  asm volatile("mbarrier.init.shared.b64 [%0], %1;" :: "r"(a), "r"(cnt) : "memory");
}
__device__ __forceinline__ void bar_arrive(uint32_t a) {
  asm volatile("mbarrier.arrive.shared.b64 _, [%0];" :: "r"(a) : "memory");
}
__device__ __forceinline__ void bar_expect_tx(uint32_t a, uint32_t tx) {
  asm volatile("mbarrier.arrive.expect_tx.shared.b64 _, [%0], %1;" :: "r"(a), "r"(tx) : "memory");
}
__device__ __forceinline__ void bar_wait(uint32_t a, uint32_t parity) {
  asm volatile(
    "{\n\t.reg .pred P;\n\t"
    "BW_%=:\n\t"
    "mbarrier.try_wait.parity.shared.b64 P, [%0], %1, 0x989680;\n\t"
    "@!P bra BW_%=;\n\t}"
    :: "r"(a), "r"(parity) : "memory");
}
__device__ __forceinline__ void tma2d(uint32_t dst, const void* map, int cx, int cy, uint32_t bar) {
  asm volatile(
    "cp.async.bulk.tensor.2d.shared::cluster.global.tile.mbarrier::complete_tx::bytes "
    "[%0], [%1, {%2, %3}], [%4];"
    :: "r"(dst), "l"(map), "r"(cx), "r"(cy), "r"(bar) : "memory");
}

#define SWZ(o) ((o) ^ (((o) >> 3) & 0x70))

#define LDMX4(r, addr)                                                        \
  asm volatile("ldmatrix.sync.aligned.m8n8.x4.shared.b16 {%0,%1,%2,%3}, [%4];"\
               : "=r"((r)[0]), "=r"((r)[1]), "=r"((r)[2]), "=r"((r)[3])       \
               : "r"(addr))

#define MMA16816(d, a, b)                                                     \
  asm volatile("mma.sync.aligned.m16n8k16.row.col.f32.f16.f16.f32 "           \
               "{%0,%1,%2,%3}, {%4,%5,%6,%7}, {%8,%9}, {%0,%1,%2,%3};"        \
               : "+f"((d)[0]), "+f"((d)[1]), "+f"((d)[2]), "+f"((d)[3])       \
               : "r"((a)[0]), "r"((a)[1]), "r"((a)[2]), "r"((a)[3]),          \
                 "r"((b)[0]), "r"((b)[1]))

// ============================================================
// k_pre: ALL independent prep in one launch (heterogeneous blocks).
//   b in [0,256)      : W2 = O*U*S
//   b in [256,512)    : G = V V^T
//   b in [512,520)    : V -> fp16
//   b in [520,1032)   : W fp32 -> g_wa fp16 + ||row||^2 + pads (ldcs reads)
//   b in [1032,33800) : x fp32 -> g_xa fp16 (div-free, ldcs/stcs streaming)
// ============================================================
__global__ void k_pre(const float* __restrict__ x, const float* __restrict__ W,
                      const float* __restrict__ U, const float* __restrict__ V,
                      const float* __restrict__ S, const float* __restrict__ O) {
  const int b = blockIdx.x, tid = threadIdx.x;
  if (b < 256) {
    int idx = b * 256 + tid;
    int o = idx >> 4, r = idx & 15;
    g_W2[idx] = O[o] * U[idx] * S[r];
  } else if (b < 512) {
    const int p = b - 256, r = p >> 4, r2 = p & 15;
    const float4* va = (const float4*)(V + r  * K_DIM);
    const float4* vb = (const float4*)(V + r2 * K_DIM);
    float s = 0.f;
    for (int i = tid; i < 1024; i += 256) {
      float4 a = va[i], c = vb[i];
      s += a.x * c.x + a.y * c.y + a.z * c.z + a.w * c.w;
    }
    __shared__ float red[256];
    red[tid] = s; __syncthreads();
#pragma unroll
    for (int st = 128; st; st >>= 1) {
      if (tid < st) red[tid] += red[tid + st];
      __syncthreads();
    }
    if (tid == 0) g_G[p] = red[0];
  } else if (b < 520) {
#pragma unroll
    for (int j = 0; j < 8; ++j) {
      int idx = (b - 512) * 8192 + j * 1024 + tid * 4;
      float4 v = *(const float4*)(V + idx);
      union { __half2 h[2]; uint2 u; } P;
      P.h[0] = __floats2half2_rn(v.x, v.y);
      P.h[1] = __floats2half2_rn(v.z, v.w);
      *(uint2*)(g_vh + idx) = P.u;
    }
  } else if (b < 1032) {
    const int lane = tid & 31, warp = tid >> 5;
    const int row = (b - 520) * 8 + warp;
    const float* src = W + (size_t)row * K_DIM;
    __half* dst = g_wa + (size_t)row * KA;
    float nacc = 0.f;
#pragma unroll 8
    for (int i = 0; i < 32; ++i) {
      float4 v = __ldcs((const float4*)(src + i * 128 + lane * 4));
      nacc += v.x * v.x + v.y * v.y + v.z * v.z + v.w * v.w;
      union { __half2 h[2]; uint2 u; } P;
      P.h[0] = __floats2half2_rn(v.x, v.y);
      P.h[1] = __floats2half2_rn(v.z, v.w);
      *(uint2*)(dst + i * 128 + lane * 4) = P.u;
    }
#pragma unroll
    for (int off = 16; off; off >>= 1) nacc += __shfl_xor_sync(0xffffffffu, nacc, off);
    if (lane == 0) g_nb[row] = nacc;
    if (lane < 6) *(uint4*)(dst + 4112 + lane * 8) = make_uint4(0, 0, 0, 0);
  } else {
    // x split: 2 blocks per row, div-free; streaming hints both directions.
    const int idx = b - 1032;                  // 0 .. 32767
    const int row = idx >> 1;
    const int g = ((idx & 1) << 8) + tid;      // 0..511
    const float4* src = (const float4*)(x + (size_t)row * K_DIM + g * 8);
    float4 v0 = __ldcs(src);
    float4 v1 = __ldcs(src + 1);
    union { __half2 h[4]; uint4 u; } H;
    H.h[0] = __floats2half2_rn(v0.x, v0.y);
    H.h[1] = __floats2half2_rn(v0.z, v0.w);
    H.h[2] = __floats2half2_rn(v1.x, v1.y);
    H.h[3] = __floats2half2_rn(v1.z, v1.w);
    __stcs((uint4*)(g_xa + (size_t)row * KA + g * 8), H.u);
    if ((idx & 1) && tid < 8)   // zero t-region (overwritten by k_t) + pads
      *(uint4*)(g_xa + (size_t)row * KA + (512 + tid) * 8) = make_uint4(0, 0, 0, 0);
  }
}

// ============================================================
// k_t: 64 rows/block, 128 threads, 4 warps (exact R14 version).
// blocks 0..255 : t -> fp16 into g_xa cols 4096..4111
// blocks 256..319: d -> g_d fp32
// ============================================================
__global__ void __launch_bounds__(128) k_t() {
  __shared__ __align__(16) __half As[2][64 * 72];
  __shared__ __align__(16) __half Vs[2][16 * 72];
  const int tid = threadIdx.x, lane = tid & 31, warp = tid >> 5;
  const bool isw = blockIdx.x >= 256;
  const int row0 = (isw ? (int)blockIdx.x - 256 : (int)blockIdx.x) * 64;
  const __half* A = isw ? g_wa : g_xa;

  auto load = [&](int s, int kc) {
    const int k0 = kc * 64;
    const uint32_t ab = smem_u32(&As[s][0]);
#pragma unroll
    for (int i = 0; i < 4; ++i) {
      int c = i * 128 + tid, r = c >> 3, q = c & 7;
      cpa16(ab + (uint32_t)(r * 72 + q * 8) * 2,
            A + (size_t)(row0 + r) * KA + k0 + q * 8);
    }
    {
      int r = tid >> 3, q = tid & 7;
      cpa16(smem_u32(&Vs[s][0]) + (uint32_t)(r * 72 + q * 8) * 2,
            g_vh + r * K_DIM + k0 + q * 8);
    }
  };

  float acc[2][4];
#pragma unroll
  for (int i = 0; i < 2; ++i)
#pragma unroll
    for (int e = 0; e < 4; ++e) acc[i][e] = 0.f;

  load(0, 0);
  asm volatile("cp.async.commit_group;" ::: "memory");

  const int arow = lane & 15, acol = (lane >> 4) << 3;
  const int brow = (lane & 7) + ((lane >> 4) << 3), bcol = ((lane >> 3) & 1) << 3;

  for (int kc = 0; kc < 64; ++kc) {
    if (kc + 1 < 64) load((kc + 1) & 1, kc + 1);
    asm volatile("cp.async.commit_group;" ::: "memory");
    asm volatile("cp.async.wait_group 1;" ::: "memory");
    __syncthreads();
    const uint32_t aB = smem_u32(&As[kc & 1][0]);
    const uint32_t bB = smem_u32(&Vs[kc & 1][0]);
#pragma unroll
    for (int kk = 0; kk < 4; ++kk) {
      uint32_t a[4], bt[4];
      LDMX4(a, aB + (uint32_t)((warp * 16 + arow) * 72 + kk * 16 + acol) * 2);
      LDMX4(bt, bB + (uint32_t)(brow * 72 + kk * 16 + bcol) * 2);
      uint32_t b0[2] = {bt[0], bt[1]}, b1[2] = {bt[2], bt[3]};
      MMA16816(acc[0], a, b0);
      MMA16816(acc[1], a, b1);
    }
    __syncthreads();
  }

  const int r1 = row0 + warp * 16 + (lane >> 2);
#pragma unroll
  for (int nt = 0; nt < 2; ++nt) {
    const int c = nt * 8 + 2 * (lane & 3);
    if (isw) {
      *(float2*)&g_d[(size_t)r1 * 16 + c]       = make_float2(acc[nt][0], acc[nt][1]);
      *(float2*)&g_d[(size_t)(r1 + 8) * 16 + c] = make_float2(acc[nt][2], acc[nt][3]);
    } else {
      *(__half2*)&g_xa[(size_t)r1 * KA + 4096 + c]       = __floats2half2_rn(acc[nt][0], acc[nt][1]);
      *(__half2*)&g_xa[(size_t)(r1 + 8) * KA + 4096 + c] = __floats2half2_rn(acc[nt][2], acc[nt][3]);
    }
  }
}

// ============================================================
// k_sw: merged scale + wscale, one warp per row (exact R14).
// ============================================================
__global__ void k_sw(const float* __restrict__ mag) {
  const int lane = threadIdx.x & 31, warp = threadIdx.x >> 5;
  const int row = blockIdx.x * 8 + warp;

  float p = 0.f;
  if (lane < 16) {
    const float w2r = g_W2[row * 16 + lane];
    float gsum = 0.f;
#pragma unroll
    for (int r2 = 0; r2 < 16; ++r2)
      gsum += g_G[lane * 16 + r2] * g_W2[row * 16 + r2];
    p = w2r * (2.f * g_d[row * 16 + lane] + gsum);
  }
#pragma unroll
  for (int off = 16; off; off >>= 1) p += __shfl_xor_sync(0xffffffffu, p, off);
  const float sc = mag[row] / sqrtf(g_nb[row] + p);
  const float s = sc - 1.f;

  __half* dst = g_wa + (size_t)row * KA;
#pragma unroll 4
  for (int i = 0; i < 16; ++i) {
    uint4 u = *(uint4*)(dst + (i * 32 + lane) * 8);
    union { __half2 h[4]; uint4 u; } P;
    P.u = u;
#pragma unroll
    for (int j = 0; j < 4; ++j) {
      float2 f = __half22float2(P.h[j]);
      P.h[j] = __floats2half2_rn(f.x * s, f.y * s);
    }
    *(uint4*)(dst + (i * 32 + lane) * 8) = P.u;
  }
  if (lane < 2) {
    union { __half2 h[4]; uint4 u; } P;
#pragma unroll
    for (int j = 0; j < 4; ++j) {
      int r = lane * 8 + j * 2;
      P.h[j] = __floats2half2_rn(sc * g_W2[row * 16 + r], sc * g_W2[row * 16 + r + 1]);
    }
    *(uint4*)(dst + 4096 + lane * 8) = P.u;
  }
}

// ============================================================
// k_gemm_h: EXACT R9/R14 kernel (best measured — do not touch).
// ============================================================
#define BMt 256
#define BNt 128
#define BKh 64
#define NKTt (KA / BKh)                  // 65
#define A_BYTES (BMt * 128)              // 32768
#define B_BYTES (BNt * 128)              // 16384
#define STAGE_B (A_BYTES + B_BYTES)      // 49152
#define NSTG 4
#define GEMM_SMEM (NSTG * STAGE_B + 1024)  // 197632

__global__ void __launch_bounds__(256, 1)
k_gemm_h(const __grid_constant__ CUtensorMap mapA,
         const __grid_constant__ CUtensorMap mapB,
         float* __restrict__ out) {
  extern __shared__ __align__(16) uint8_t dynsm[];
  __shared__ __align__(8) uint64_t s_bar[8];  // full[4], empty[4]

  const int tid  = threadIdx.x;
  const int lane = tid & 31;
  const int warp = tid >> 5;
  const int m_base = (warp >> 1) * 64;
  const int n_base = (warp & 1) * 64;
  const int bM = blockIdx.y * BMt;
  const int bN = blockIdx.x * BNt;

  const uint32_t raw = smem_u32(dynsm);
  const uint32_t smb = (raw + 1023u) & ~1023u;
  const uint32_t barb = smem_u32(s_bar);

  if (tid == 0) {
#pragma unroll
    for (int s = 0; s < NSTG; ++s) {
      bar_init(barb + s * 8, 1);               // full (tx-based)
      bar_init(barb + NSTG * 8 + s * 8, 8);    // empty (one arrive per warp)
    }
  }
  __syncthreads();
  if (lane == 0) {
#pragma unroll
    for (int s = 0; s < NSTG; ++s) bar_arrive(barb + NSTG * 8 + s * 8);  // pre-arm
  }

  // prefill stages 0..2
  if (tid == 0) {
#pragma unroll
    for (int p = 0; p < 3; ++p) {
      const uint32_t fb = barb + p * 8;
      bar_wait(barb + NSTG * 8 + p * 8, 0);
      bar_expect_tx(fb, STAGE_B);
      const uint32_t base = smb + p * STAGE_B;
      tma2d(base,           &mapA, p * BKh, bM, fb);
      tma2d(base + A_BYTES, &mapB, p * BKh, bN, fb);
    }
  }

  float acc[4][8][4];
#pragma unroll
  for (int i = 0; i < 4; ++i)
#pragma unroll
    for (int j = 0; j < 8; ++j)
#pragma unroll
      for (int e = 0; e < 4; ++e) acc[i][j][e] = 0.f;

  const int arow = lane & 15;
  const int ahalf = lane >> 4;
  const int brow = (lane & 7) + ((lane >> 4) << 3);
  const int bhalf = (lane >> 3) & 1;

  uint32_t ah[2][4][4], bh[2][8][2];

  auto lds_frags = [&](int buf, uint32_t aB, uint32_t bB, int kk) {
#pragma unroll
    for (int mt = 0; mt < 4; ++mt) {
      const uint32_t off = (uint32_t)((m_base + mt * 16 + arow) * 128 +
                                      (kk * 2 + ahalf) * 16);
      LDMX4(ah[buf][mt], aB + SWZ(off));
    }
#pragma unroll
    for (int pp = 0; pp < 4; ++pp) {
      const uint32_t off = (uint32_t)((n_base + pp * 16 + brow) * 128 +
                                      (kk * 2 + bhalf) * 16);
      uint32_t r[4];
      LDMX4(r, bB + SWZ(off));
      bh[buf][2 * pp][0] = r[0]; bh[buf][2 * pp][1] = r[1];
      bh[buf][2 * pp + 1][0] = r[2]; bh[buf][2 * pp + 1][1] = r[3];
    }
  };

  for (int kt = 0; kt < NKTt; ++kt) {
    const int p = kt + 3;
    if (tid == 0 && p < NKTt) {
      const int sp = p & 3;
      const uint32_t fb = barb + sp * 8;
      bar_wait(barb + NSTG * 8 + sp * 8, (p >> 2) & 1);
      bar_expect_tx(fb, STAGE_B);
      const uint32_t base = smb + sp * STAGE_B;
      tma2d(base,           &mapA, p * BKh, bM, fb);
      tma2d(base + A_BYTES, &mapB, p * BKh, bN, fb);
    }
    const int s = kt & 3;
    bar_wait(barb + s * 8, (kt >> 2) & 1);

    const uint32_t aB = smb + s * STAGE_B;
    const uint32_t bB = aB + A_BYTES;

    lds_frags(0, aB, bB, 0);
#pragma unroll
    for (int kk = 0; kk < 4; ++kk) {
      const int cur = kk & 1;
      if (kk < 3) lds_frags(cur ^ 1, aB, bB, kk + 1);
#pragma unroll
      for (int mt = 0; mt < 4; ++mt)
#pragma unroll
        for (int nt = 0; nt < 8; ++nt)
          MMA16816(acc[mt][nt], ah[cur][mt], bh[cur][nt]);
    }
    if (lane == 0) bar_arrive(barb + NSTG * 8 + s * 8);
  }

  // ---------------- pure store ----------------
#pragma unroll
  for (int mt = 0; mt < 4; ++mt)
#pragma unroll
    for (int h = 0; h < 2; ++h) {
      const int gm = bM + m_base + mt * 16 + h * 8 + (lane >> 2);
#pragma unroll
      for (int nt = 0; nt < 8; ++nt) {
        const int gn = bN + n_base + nt * 8 + 2 * (lane & 3);
        *(float2*)(out + (size_t)gm * N_DIM + gn) =
            make_float2(acc[mt][nt][h * 2], acc[mt][nt][h * 2 + 1]);
      }
    }
}

// ============================================================
typedef CUresult (*EncTiledFn)(
    CUtensorMap*, CUtensorMapDataType, cuuint32_t, void*,
    const cuuint64_t*, const cuuint64_t*, const cuuint32_t*, const cuuint32_t*,
    CUtensorMapInterleave, CUtensorMapSwizzle, CUtensorMapL2promotion,
    CUtensorMapFloatOOBfill);

extern "C" void kernel_launch(void* const* d_in, const int* in_sizes, int n_in,
                              void* d_out, int out_size) {
  (void)in_sizes; (void)n_in; (void)out_size;
  const float* x   = (const float*)d_in[0];
  const float* U   = (const float*)d_in[1];
  const float* V   = (const float*)d_in[2];
  const float* S   = (const float*)d_in[3];
  const float* O   = (const float*)d_in[4];
  const float* mag = (const float*)d_in[5];
  const float* W   = (const float*)d_in[6];
  float* out = (float*)d_out;

  cudaFuncSetAttribute(k_gemm_h, cudaFuncAttributeMaxDynamicSharedMemorySize, GEMM_SMEM);

  void* fn = nullptr;
  cudaDriverEntryPointQueryResult qr;
  cudaGetDriverEntryPointByVersion("cuTensorMapEncodeTiled", &fn, 12000,
                                   cudaEnableDefault, &qr);
  EncTiledFn enc = (EncTiledFn)fn;
  void *pxa, *pwa;
  cudaGetSymbolAddress(&pxa, g_xa);
  cudaGetSymbolAddress(&pwa, g_wa);

  CUtensorMap mA, mB;
  {
    cuuint64_t dims[2]  = {(cuuint64_t)KA, (cuuint64_t)M_DIM};
    cuuint64_t strd[1]  = {(cuuint64_t)KA * 2};
    cuuint32_t box[2]   = {BKh, BMt};
    cuuint32_t es[2]    = {1, 1};
    enc(&mA, CU_TENSOR_MAP_DATA_TYPE_FLOAT16, 2, pxa, dims, strd, box, es,
        CU_TENSOR_MAP_INTERLEAVE_NONE, CU_TENSOR_MAP_SWIZZLE_128B,
        CU_TENSOR_MAP_L2_PROMOTION_L2_128B, CU_TENSOR_MAP_FLOAT_OOB_FILL_NONE);
  }
  {
    cuuint64_t dims[2]  = {(cuuint64_t)KA, (cuuint64_t)N_DIM};
    cuuint64_t strd[1]  = {(cuuint64_t)KA * 2};
    cuuint32_t box[2]   = {BKh, BNt};
    cuuint32_t es[2]    = {1, 1};
    enc(&mB, CU_TENSOR_MAP_DATA_TYPE_FLOAT16, 2, pwa, dims, strd, box, es,
        CU_TENSOR_MAP_INTERLEAVE_NONE, CU_TENSOR_MAP_SWIZZLE_128B,
        CU_TENSOR_MAP_L2_PROMOTION_L2_128B, CU_TENSOR_MAP_FLOAT_OOB_FILL_NONE);
  }

  k_pre<<<33800, 256>>>(x, W, U, V, S, O);        // 1 (merged prep, streaming)
  k_t<<<320, 128>>>();                            // 2 (high-occupancy)
  k_sw<<<N_DIM / 8, 256>>>(mag);                  // 3
  k_gemm_h<<<dim3(N_DIM / BNt, M_DIM / BMt), 256, GEMM_SMEM>>>(mA, mB, out);  // 4 (R9)
}

// round 17
// speedup vs baseline: 1.0589x; 1.0067x over previous
#include <cuda_runtime.h>
#include <cuda.h>
#include <cuda_fp16.h>
#include <cstdint>

#define M_DIM 16384
#define N_DIM 4096
#define K_DIM 4096
#define R_DIM 16
#define KA    4160   // K augmented: 4096 base + 16 low-rank + 48 zero pad

// ---- device scratch (module-load allocated; no runtime allocs) ----
__device__ float g_W2 [N_DIM * R_DIM];
__device__ float g_G  [R_DIM * R_DIM];
__device__ float g_d  [N_DIM * R_DIM];
__device__ float g_nb [N_DIM];
__device__ __half g_xa[(size_t)M_DIM * KA];   // [x_fp16 | t | 0pad]
__device__ __half g_wa[(size_t)N_DIM * KA];   // [(sc-1)*w_fp16 | sc*W2 | 0pad]

__device__ __forceinline__ uint32_t smem_u32(const void* p) {
  uint32_t a;
  asm("{ .reg .u64 t; cvta.to.shared.u64 t, %1; cvt.u32.u64 %0, t; }" : "=r"(a) : "l"(p));
  return a;
}
__device__ __forceinline__ void cpa16(uint32_t dst, const void* src) {
  asm volatile("cp.async.cg.shared.global [%0], [%1], 16;" :: "r"(dst), "l"(src) : "memory");
}
__device__ __forceinline__ void bar_init(uint32_t a, uint32_t cnt) {
  asm volatile("mbarrier.init.shared.b64 [%0], %1;" :: "r"(a), "r"(cnt) : "memory");
}
__device__ __forceinline__ void bar_arrive(uint32_t a) {
  asm volatile("mbarrier.arrive.shared.b64 _, [%0];" :: "r"(a) : "memory");
}
__device__ __forceinline__ void bar_expect_tx(uint32_t a, uint32_t tx) {
  asm volatile("mbarrier.arrive.expect_tx.shared.b64 _, [%0], %1;" :: "r"(a), "r"(tx) : "memory");
}
__device__ __forceinline__ void bar_wait(uint32_t a, uint32_t parity) {
  asm volatile(
    "{\n\t.reg .pred P;\n\t"
    "BW_%=:\n\t"
    "mbarrier.try_wait.parity.shared.b64 P, [%0], %1, 0x989680;\n\t"
    "@!P bra BW_%=;\n\t}"
    :: "r"(a), "r"(parity) : "memory");
}
__device__ __forceinline__ void tma2d(uint32_t dst, const void* map, int cx, int cy, uint32_t bar) {
  asm volatile(
    "cp.async.bulk.tensor.2d.shared::cluster.global.tile.mbarrier::complete_tx::bytes "
    "[%0], [%1, {%2, %3}], [%4];"
    :: "r"(dst), "l"(map), "r"(cx), "r"(cy), "r"(bar) : "memory");
}

#define SWZ(o) ((o) ^ (((o) >> 3) & 0x70))

#define LDMX4(r, addr)                                                        \
  asm volatile("ldmatrix.sync.aligned.m8n8.x4.shared.b16 {%0,%1,%2,%3}, [%4];"\
               : "=r"((r)[0]), "=r"((r)[1]), "=r"((r)[2]), "=r"((r)[3])       \
               : "r"(addr))

#define MMA16816(d, a, b)                                                     \
  asm volatile("mma.sync.aligned.m16n8k16.row.col.f32.f16.f16.f32 "           \
               "{%0,%1,%2,%3}, {%4,%5,%6,%7}, {%8,%9}, {%0,%1,%2,%3};"        \
               : "+f"((d)[0]), "+f"((d)[1]), "+f"((d)[2]), "+f"((d)[3])       \
               : "r"((a)[0]), "r"((a)[1]), "r"((a)[2]), "r"((a)[3]),          \
                 "r"((b)[0]), "r"((b)[1]))

// ============================================================
// k_pre: W2 = O*U*S (blocks 0..255) ; G = V V^T (blocks 256..511)
// ============================================================
__global__ void k_pre(const float* __restrict__ U, const float* __restrict__ V,
                      const float* __restrict__ S, const float* __restrict__ O) {
  const int b = blockIdx.x, tid = threadIdx.x;
  if (b < 256) {
    int idx = b * 256 + tid;
    int o = idx >> 4, r = idx & 15;
    g_W2[idx] = O[o] * U[idx] * S[r];
  } else {
    const int p = b - 256, r = p >> 4, r2 = p & 15;
    const float4* va = (const float4*)(V + r  * K_DIM);
    const float4* vb = (const float4*)(V + r2 * K_DIM);
    float s = 0.f;
    for (int i = tid; i < 1024; i += 256) {
      float4 a = va[i], c = vb[i];
      s += a.x * c.x + a.y * c.y + a.z * c.z + a.w * c.w;
    }
    __shared__ float red[256];
    red[tid] = s; __syncthreads();
#pragma unroll
    for (int st = 128; st; st >>= 1) {
      if (tid < st) red[tid] += red[tid + st];
      __syncthreads();
    }
    if (tid == 0) g_G[p] = red[0];
  }
}

// ============================================================
// k_t3: FUSED split + rowdot with cp.async fp32 staging (R14 k_t's
// pipeline pattern preserved). 64 rows/block, 128 threads, 4 warps.
//  blocks 0..255 : x -> g_xa fp16, t = xh@Vh^T -> g_xa cols 4096+
//  blocks 256..319: W -> g_wa fp16, d -> g_d, ||row||^2 -> g_nb
// V staged fp32 per chunk (L2-resident). Pads zeroed in epilogue.
// fp16 values + MMA order identical to R14 k_t.
// ============================================================
#define FSTR 68   // fp32 smem row stride (floats)

__global__ void __launch_bounds__(128) k_t3(const float* __restrict__ x,
                                            const float* __restrict__ W,
                                            const float* __restrict__ V) {
  __shared__ __align__(16) float Xf[2][64 * FSTR];
  __shared__ __align__(16) float Vf[2][16 * FSTR];
  __shared__ __align__(16) __half As[64 * 72];
  __shared__ __align__(16) __half Vs[16 * 72];

  const int tid = threadIdx.x, lane = tid & 31, warp = tid >> 5;
  const bool isw = blockIdx.x >= 256;
  const int row0 = (isw ? (int)blockIdx.x - 256 : (int)blockIdx.x) * 64;
  const float* A = isw ? W : x;
  __half* dstg = isw ? g_wa : g_xa;

  // cp.async stage loader: A 64x64 fp32 (1024 float4) + V 16x64 (256 float4)
  auto load = [&](int s, int kc) {
    const int k0 = kc * 64;
    const uint32_t xb = smem_u32(&Xf[s][0]);
#pragma unroll
    for (int i = 0; i < 8; ++i) {
      const int c = i * 128 + tid;            // 0..1023
      const int r = c >> 4, f4 = c & 15;
      cpa16(xb + (uint32_t)(r * FSTR + f4 * 4) * 4,
            A + (size_t)(row0 + r) * K_DIM + k0 + f4 * 4);
    }
    const uint32_t vb = smem_u32(&Vf[s][0]);
#pragma unroll
    for (int i = 0; i < 2; ++i) {
      const int c = i * 128 + tid;            // 0..255
      const int r = c >> 4, f4 = c & 15;
      cpa16(vb + (uint32_t)(r * FSTR + f4 * 4) * 4,
            V + (size_t)r * K_DIM + k0 + f4 * 4);
    }
  };

  float acc[2][4];
#pragma unroll
  for (int i = 0; i < 2; ++i)
#pragma unroll
    for (int e = 0; e < 4; ++e) acc[i][e] = 0.f;
  float nacc[4] = {0.f, 0.f, 0.f, 0.f};

  const int rr = tid >> 3;        // 0..15
  const int q  = tid & 7;         // 0..7
  const int arow = lane & 15, acol = (lane >> 4) << 3;
  const int brow = (lane & 7) + ((lane >> 4) << 3), bcol = ((lane >> 3) & 1) << 3;
  const uint32_t aB = smem_u32(As);
  const uint32_t bB = smem_u32(Vs);

  load(0, 0);
  asm volatile("cp.async.commit_group;" ::: "memory");

  for (int kc = 0; kc < 64; ++kc) {
    if (kc + 1 < 64) load((kc + 1) & 1, kc + 1);
    asm volatile("cp.async.commit_group;" ::: "memory");
    asm volatile("cp.async.wait_group 1;" ::: "memory");
    __syncthreads();

    const int s = kc & 1;
    const int k0 = kc * 64;
    // ---- convert: smem fp32 -> smem fp16 + gmem fp16 (+ norms) ----
#pragma unroll
    for (int i = 0; i < 4; ++i) {
      const int r = i * 16 + rr;
      const float* src = &Xf[s][r * FSTR + q * 8];
      float4 v0 = *(const float4*)src;
      float4 v1 = *(const float4*)(src + 4);
      if (isw)
        nacc[i] += v0.x * v0.x + v0.y * v0.y + v0.z * v0.z + v0.w * v0.w +
                   v1.x * v1.x + v1.y * v1.y + v1.z * v1.z + v1.w * v1.w;
      union { __half2 h[4]; uint4 u; } H;
      H.h[0] = __floats2half2_rn(v0.x, v0.y);
      H.h[1] = __floats2half2_rn(v0.z, v0.w);
      H.h[2] = __floats2half2_rn(v1.x, v1.y);
      H.h[3] = __floats2half2_rn(v1.z, v1.w);
      *(uint4*)&As[r * 72 + q * 8] = H.u;
      *(uint4*)(dstg + (size_t)(row0 + r) * KA + k0 + q * 8) = H.u;
    }
    {
      const float* src = &Vf[s][rr * FSTR + q * 8];
      float4 v0 = *(const float4*)src;
      float4 v1 = *(const float4*)(src + 4);
      union { __half2 h[4]; uint4 u; } H;
      H.h[0] = __floats2half2_rn(v0.x, v0.y);
      H.h[1] = __floats2half2_rn(v0.z, v0.w);
      H.h[2] = __floats2half2_rn(v1.x, v1.y);
      H.h[3] = __floats2half2_rn(v1.z, v1.w);
      *(uint4*)&Vs[rr * 72 + q * 8] = H.u;
    }
    __syncthreads();

    // ---- MMA (identical layout/order to R14 k_t) ----
#pragma unroll
    for (int kk = 0; kk < 4; ++kk) {
      uint32_t a[4], bt[4];
      LDMX4(a, aB + (uint32_t)((warp * 16 + arow) * 72 + kk * 16 + acol) * 2);
      LDMX4(bt, bB + (uint32_t)(brow * 72 + kk * 16 + bcol) * 2);
      uint32_t b0[2] = {bt[0], bt[1]}, b1[2] = {bt[2], bt[3]};
      MMA16816(acc[0], a, b0);
      MMA16816(acc[1], a, b1);
    }
  }

  // ---- norm reduce + store (W blocks) ----
  if (isw) {
#pragma unroll
    for (int i = 0; i < 4; ++i) {
      float v = nacc[i];
#pragma unroll
      for (int off = 4; off; off >>= 1) v += __shfl_xor_sync(0xffffffffu, v, off);
      if (q == 0) g_nb[row0 + i * 16 + rr] = v;
    }
  }

  // ---- t / d store ----
  const int r1 = row0 + warp * 16 + (lane >> 2);
#pragma unroll
  for (int nt = 0; nt < 2; ++nt) {
    const int c = nt * 8 + 2 * (lane & 3);
    if (isw) {
      *(float2*)&g_d[(size_t)r1 * 16 + c]       = make_float2(acc[nt][0], acc[nt][1]);
      *(float2*)&g_d[(size_t)(r1 + 8) * 16 + c] = make_float2(acc[nt][2], acc[nt][3]);
    } else {
      *(__half2*)&g_xa[(size_t)r1 * KA + 4096 + c]       = __floats2half2_rn(acc[nt][0], acc[nt][1]);
      *(__half2*)&g_xa[(size_t)(r1 + 8) * KA + 4096 + c] = __floats2half2_rn(acc[nt][2], acc[nt][3]);
    }
  }

  // ---- zero pads: cols 4112..4159 (6 x uint4 per row, 64 rows) ----
#pragma unroll
  for (int j = 0; j < 3; ++j) {
    const int idx = j * 128 + tid;        // 0..383
    const int r = idx / 6, p = idx % 6;
    *(uint4*)(dstg + (size_t)(row0 + r) * KA + 4112 + p * 8) = make_uint4(0, 0, 0, 0);
  }
}

// ============================================================
// k_sw: merged scale + wscale, one warp per row (exact R14).
// ============================================================
__global__ void k_sw(const float* __restrict__ mag) {
  const int lane = threadIdx.x & 31, warp = threadIdx.x >> 5;
  const int row = blockIdx.x * 8 + warp;

  float p = 0.f;
  if (lane < 16) {
    const float w2r = g_W2[row * 16 + lane];
    float gsum = 0.f;
#pragma unroll
    for (int r2 = 0; r2 < 16; ++r2)
      gsum += g_G[lane * 16 + r2] * g_W2[row * 16 + r2];
    p = w2r * (2.f * g_d[row * 16 + lane] + gsum);
  }
#pragma unroll
  for (int off = 16; off; off >>= 1) p += __shfl_xor_sync(0xffffffffu, p, off);
  const float sc = mag[row] / sqrtf(g_nb[row] + p);
  const float s = sc - 1.f;

  __half* dst = g_wa + (size_t)row * KA;
#pragma unroll 4
  for (int i = 0; i < 16; ++i) {
    uint4 u = *(uint4*)(dst + (i * 32 + lane) * 8);
    union { __half2 h[4]; uint4 u; } P;
    P.u = u;
#pragma unroll
    for (int j = 0; j < 4; ++j) {
      float2 f = __half22float2(P.h[j]);
      P.h[j] = __floats2half2_rn(f.x * s, f.y * s);
    }
    *(uint4*)(dst + (i * 32 + lane) * 8) = P.u;
  }
  if (lane < 2) {
    union { __half2 h[4]; uint4 u; } P;
#pragma unroll
    for (int j = 0; j < 4; ++j) {
      int r = lane * 8 + j * 2;
      P.h[j] = __floats2half2_rn(sc * g_W2[row * 16 + r], sc * g_W2[row * 16 + r + 1]);
    }
    *(uint4*)(dst + 4096 + lane * 8) = P.u;
  }
}

// ============================================================
// k_gemm_h: EXACT R9/R14 kernel (best measured — do not touch).
// ============================================================
#define BMt 256
#define BNt 128
#define BKh 64
#define NKTt (KA / BKh)                  // 65
#define A_BYTES (BMt * 128)              // 32768
#define B_BYTES (BNt * 128)              // 16384
#define STAGE_B (A_BYTES + B_BYTES)      // 49152
#define NSTG 4
#define GEMM_SMEM (NSTG * STAGE_B + 1024)  // 197632

__global__ void __launch_bounds__(256, 1)
k_gemm_h(const __grid_constant__ CUtensorMap mapA,
         const __grid_constant__ CUtensorMap mapB,
         float* __restrict__ out) {
  extern __shared__ __align__(16) uint8_t dynsm[];
  __shared__ __align__(8) uint64_t s_bar[8];  // full[4], empty[4]

  const int tid  = threadIdx.x;
  const int lane = tid & 31;
  const int warp = tid >> 5;
  const int m_base = (warp >> 1) * 64;
  const int n_base = (warp & 1) * 64;
  const int bM = blockIdx.y * BMt;
  const int bN = blockIdx.x * BNt;

  const uint32_t raw = smem_u32(dynsm);
  const uint32_t smb = (raw + 1023u) & ~1023u;
  const uint32_t barb = smem_u32(s_bar);

  if (tid == 0) {
#pragma unroll
    for (int s = 0; s < NSTG; ++s) {
      bar_init(barb + s * 8, 1);               // full (tx-based)
      bar_init(barb + NSTG * 8 + s * 8, 8);    // empty (one arrive per warp)
    }
  }
  __syncthreads();
  if (lane == 0) {
#pragma unroll
    for (int s = 0; s < NSTG; ++s) bar_arrive(barb + NSTG * 8 + s * 8);  // pre-arm
  }

  // prefill stages 0..2
  if (tid == 0) {
#pragma unroll
    for (int p = 0; p < 3; ++p) {
      const uint32_t fb = barb + p * 8;
      bar_wait(barb + NSTG * 8 + p * 8, 0);
      bar_expect_tx(fb, STAGE_B);
      const uint32_t base = smb + p * STAGE_B;
      tma2d(base,           &mapA, p * BKh, bM, fb);
      tma2d(base + A_BYTES, &mapB, p * BKh, bN, fb);
    }
  }

  float acc[4][8][4];
#pragma unroll
  for (int i = 0; i < 4; ++i)
#pragma unroll
    for (int j = 0; j < 8; ++j)
#pragma unroll
      for (int e = 0; e < 4; ++e) acc[i][j][e] = 0.f;

  const int arow = lane & 15;
  const int ahalf = lane >> 4;
  const int brow = (lane & 7) + ((lane >> 4) << 3);
  const int bhalf = (lane >> 3) & 1;

  uint32_t ah[2][4][4], bh[2][8][2];

  auto lds_frags = [&](int buf, uint32_t aB, uint32_t bB, int kk) {
#pragma unroll
    for (int mt = 0; mt < 4; ++mt) {
      const uint32_t off = (uint32_t)((m_base + mt * 16 + arow) * 128 +
                                      (kk * 2 + ahalf) * 16);
      LDMX4(ah[buf][mt], aB + SWZ(off));
    }
#pragma unroll
    for (int pp = 0; pp < 4; ++pp) {
      const uint32_t off = (uint32_t)((n_base + pp * 16 + brow) * 128 +
                                      (kk * 2 + bhalf) * 16);
      uint32_t r[4];
      LDMX4(r, bB + SWZ(off));
      bh[buf][2 * pp][0] = r[0]; bh[buf][2 * pp][1] = r[1];
      bh[buf][2 * pp + 1][0] = r[2]; bh[buf][2 * pp + 1][1] = r[3];
    }
  };

  for (int kt = 0; kt < NKTt; ++kt) {
    const int p = kt + 3;
    if (tid == 0 && p < NKTt) {
      const int sp = p & 3;
      const uint32_t fb = barb + sp * 8;
      bar_wait(barb + NSTG * 8 + sp * 8, (p >> 2) & 1);
      bar_expect_tx(fb, STAGE_B);
      const uint32_t base = smb + sp * STAGE_B;
      tma2d(base,           &mapA, p * BKh, bM, fb);
      tma2d(base + A_BYTES, &mapB, p * BKh, bN, fb);
    }
    const int s = kt & 3;
    bar_wait(barb + s * 8, (kt >> 2) & 1);

    const uint32_t aB = smb + s * STAGE_B;
    const uint32_t bB = aB + A_BYTES;

    lds_frags(0, aB, bB, 0);
#pragma unroll
    for (int kk = 0; kk < 4; ++kk) {
      const int cur = kk & 1;
      if (kk < 3) lds_frags(cur ^ 1, aB, bB, kk + 1);
#pragma unroll
      for (int mt = 0; mt < 4; ++mt)
#pragma unroll
        for (int nt = 0; nt < 8; ++nt)
          MMA16816(acc[mt][nt], ah[cur][mt], bh[cur][nt]);
    }
    if (lane == 0) bar_arrive(barb + NSTG * 8 + s * 8);
  }

  // ---------------- pure store ----------------
#pragma unroll
  for (int mt = 0; mt < 4; ++mt)
#pragma unroll
    for (int h = 0; h < 2; ++h) {
      const int gm = bM + m_base + mt * 16 + h * 8 + (lane >> 2);
#pragma unroll
      for (int nt = 0; nt < 8; ++nt) {
        const int gn = bN + n_base + nt * 8 + 2 * (lane & 3);
        *(float2*)(out + (size_t)gm * N_DIM + gn) =
            make_float2(acc[mt][nt][h * 2], acc[mt][nt][h * 2 + 1]);
      }
    }
}

// ============================================================
typedef CUresult (*EncTiledFn)(
    CUtensorMap*, CUtensorMapDataType, cuuint32_t, void*,
    const cuuint64_t*, const cuuint64_t*, const cuuint32_t*, const cuuint32_t*,
    CUtensorMapInterleave, CUtensorMapSwizzle, CUtensorMapL2promotion,
    CUtensorMapFloatOOBfill);

extern "C" void kernel_launch(void* const* d_in, const int* in_sizes, int n_in,
                              void* d_out, int out_size) {
  (void)in_sizes; (void)n_in; (void)out_size;
  const float* x   = (const float*)d_in[0];
  const float* U   = (const float*)d_in[1];
  const float* V   = (const float*)d_in[2];
  const float* S   = (const float*)d_in[3];
  const float* O   = (const float*)d_in[4];
  const float* mag = (const float*)d_in[5];
  const float* W   = (const float*)d_in[6];
  float* out = (float*)d_out;

  cudaFuncSetAttribute(k_gemm_h, cudaFuncAttributeMaxDynamicSharedMemorySize, GEMM_SMEM);

  void* fn = nullptr;
  cudaDriverEntryPointQueryResult qr;
  cudaGetDriverEntryPointByVersion("cuTensorMapEncodeTiled", &fn, 12000,
                                   cudaEnableDefault, &qr);
  EncTiledFn enc = (EncTiledFn)fn;
  void *pxa, *pwa;
  cudaGetSymbolAddress(&pxa, g_xa);
  cudaGetSymbolAddress(&pwa, g_wa);

  CUtensorMap mA, mB;
  {
    cuuint64_t dims[2]  = {(cuuint64_t)KA, (cuuint64_t)M_DIM};
    cuuint64_t strd[1]  = {(cuuint64_t)KA * 2};
    cuuint32_t box[2]   = {BKh, BMt};
    cuuint32_t es[2]    = {1, 1};
    enc(&mA, CU_TENSOR_MAP_DATA_TYPE_FLOAT16, 2, pxa, dims, strd, box, es,
        CU_TENSOR_MAP_INTERLEAVE_NONE, CU_TENSOR_MAP_SWIZZLE_128B,
        CU_TENSOR_MAP_L2_PROMOTION_L2_128B, CU_TENSOR_MAP_FLOAT_OOB_FILL_NONE);
  }
  {
    cuuint64_t dims[2]  = {(cuuint64_t)KA, (cuuint64_t)N_DIM};
    cuuint64_t strd[1]  = {(cuuint64_t)KA * 2};
    cuuint32_t box[2]   = {BKh, BNt};
    cuuint32_t es[2]    = {1, 1};
    enc(&mB, CU_TENSOR_MAP_DATA_TYPE_FLOAT16, 2, pwa, dims, strd, box, es,
        CU_TENSOR_MAP_INTERLEAVE_NONE, CU_TENSOR_MAP_SWIZZLE_128B,
        CU_TENSOR_MAP_L2_PROMOTION_L2_128B, CU_TENSOR_MAP_FLOAT_OOB_FILL_NONE);
  }

  k_pre<<<512, 256>>>(U, V, S, O);                // 1 (W2 + G only, ~5us)
  k_t3<<<320, 128>>>(x, W, V);                    // 2 (fused, cp.async pipelined)
  k_sw<<<N_DIM / 8, 256>>>(mag);                  // 3
  k_gemm_h<<<dim3(N_DIM / BNt, M_DIM / BMt), 256, GEMM_SMEM>>>(mA, mB, out);  // 4 (R9)
}